// round 9
// baseline (speedup 1.0000x reference)
#include <cuda_runtime.h>
#include <cuda_bf16.h>
#include <math.h>

#define TT   12
#define NN   50000
#define NH   (NN * 128)
#define MT256 196           // ceil(50000/256)

// ================= scratch =================
__device__ float g_scratch[9 * NH + 65536 + 65536 + 131072 + 4096];

// ================= PTX helpers (portable, sm_80+) =================
__device__ __forceinline__ unsigned smem_u32(const void* p) {
    unsigned a;
    asm("{ .reg .u64 t; cvta.to.shared.u64 t, %1; cvt.u32.u64 %0, t; }" : "=r"(a) : "l"(p));
    return a;
}
__device__ __forceinline__ void cp16(unsigned dst, const void* src) {
    asm volatile("cp.async.cg.shared.global [%0], [%1], 16;" :: "r"(dst), "l"(src));
}
#define CP_COMMIT() asm volatile("cp.async.commit_group;" ::: "memory")
#define CP_WAIT0()  asm volatile("cp.async.wait_group 0;" ::: "memory")

#define LDSM_X4T(r0, r1, r2, r3, a) \
    asm volatile("ldmatrix.sync.aligned.m8n8.x4.trans.shared.b16 {%0,%1,%2,%3}, [%4];" \
        : "=r"(r0), "=r"(r1), "=r"(r2), "=r"(r3) : "r"(a))

#define MMA16816(d, a, b) \
    asm volatile("mma.sync.aligned.m16n8k16.row.col.f32.bf16.bf16.f32 " \
        "{%0,%1,%2,%3}, {%4,%5,%6,%7}, {%8,%9}, {%0,%1,%2,%3};" \
        : "+f"((d)[0]), "+f"((d)[1]), "+f"((d)[2]), "+f"((d)[3]) \
        : "r"((a)[0]), "r"((a)[1]), "r"((a)[2]), "r"((a)[3]), "r"((b)[0]), "r"((b)[1]))

__device__ __forceinline__ float sigf(float z) { return __fdividef(1.0f, 1.0f + __expf(-z)); }
__device__ __forceinline__ float tanhf_(float z) { return __fdividef(2.0f, 1.0f + __expf(-2.0f * z)) - 1.0f; }

// ================= prep kernels =================
__global__ void zero_k(float* p, int n) {
    int i = blockIdx.x * blockDim.x + threadIdx.x;
    if (i < n) p[i] = 0.0f;
}

// B staged layout: [y (8)][k (K)][col (64)], col = jl*4 + g, j = y*16 + jl.
__global__ void prep_all(const float* __restrict__ bih0, const float* __restrict__ bhh0,
                         const float* __restrict__ bih1, const float* __restrict__ bhh1,
                         const float* __restrict__ Whh0,
                         const float* __restrict__ Wih1, const float* __restrict__ Whh1,
                         __nv_bfloat16* __restrict__ B0h, __nv_bfloat16* __restrict__ B0l,
                         __nv_bfloat16* __restrict__ B1h, __nv_bfloat16* __restrict__ B1l,
                         float* __restrict__ bias0, float* __restrict__ bias1) {
    int idx = blockIdx.x * blockDim.x + threadIdx.x;
    if (idx < 512) {
        bias0[idx] = bih0[idx] + bhh0[idx];
        bias1[idx] = bih1[idx] + bhh1[idx];
    }
    if (idx < 8 * 128 * 64) {                 // B0 (K=128)
        int y = idx >> 13;
        int rem = idx & 8191;
        int k = rem >> 6, col = rem & 63;
        int ro = (col & 3) * 128 + y * 16 + (col >> 2);
        float w = Whh0[ro * 128 + k];
        __nv_bfloat16 hi = __float2bfloat16(w);
        B0h[idx] = hi;
        B0l[idx] = __float2bfloat16(w - __bfloat162float(hi));
    }
    if (idx < 8 * 256 * 64) {                 // B1 (K=256)
        int y = idx >> 14;
        int rem = idx & 16383;
        int k = rem >> 6, col = rem & 63;
        int ro = (col & 3) * 128 + y * 16 + (col >> 2);
        float w = (k < 128) ? Wih1[ro * 128 + k] : Whh1[ro * 128 + (k - 128)];
        __nv_bfloat16 hi = __float2bfloat16(w);
        B1h[idx] = hi;
        B1l[idx] = __float2bfloat16(w - __bfloat162float(hi));
    }
}

__global__ void deg_init(float* deg) {
    int i = blockIdx.x * blockDim.x + threadIdx.x;
    if (i < NN) deg[i] = 1.0f;
}
__global__ void deg_count(const int* __restrict__ dst, float* deg, int E) {
    int i = blockIdx.x * blockDim.x + threadIdx.x;
    if (i < E) atomicAdd(&deg[dst[i]], 1.0f);
}
__global__ void deg_rsqrt(float* deg) {
    int i = blockIdx.x * blockDim.x + threadIdx.x;
    if (i < NN) deg[i] = rsqrtf(deg[i]);
}

__global__ void recon_h(const __nv_bfloat16* __restrict__ hh, const __nv_bfloat16* __restrict__ hl,
                        float* __restrict__ out) {
    int i = blockIdx.x * blockDim.x + threadIdx.x;
    if (i < NH) out[i] = __bfloat162float(hh[i]) + __bfloat162float(hl[i]);
}

// A fragment (m16n8k16, row-major) direct from global:
// lane l: rows base+(l>>2), +8 ; cols 2*(l&3), +1, +8, +9 within the 16-k chunk.
__device__ __forceinline__ void load_frag(unsigned d[2][4], const __nv_bfloat16* __restrict__ P,
                                          const size_t offA[2][2], int koff) {
#pragma unroll
    for (int mt = 0; mt < 2; mt++) {
        d[mt][0] = *(const unsigned*)(P + offA[mt][0] + koff);
        d[mt][1] = *(const unsigned*)(P + offA[mt][1] + koff);
        d[mt][2] = *(const unsigned*)(P + offA[mt][0] + koff + 8);
        d[mt][3] = *(const unsigned*)(P + offA[mt][1] + koff + 8);
    }
}

// ================= persistent mma.sync LSTM step =================
// 512 threads = 16 warps (8 m-warps x 2 n-warps); m-tile 256 rows, 64 gate-cols.
// B (K x 64, hi+lo) block-resident smem; A fragments direct global->register,
// ping-pong double buffered (nka always even). Zero barriers in the k-loop.
// smem: B [0, K*288) ; z stage [K*288, K*288 + 73728)
template <int K, bool HASX>
__global__ __launch_bounds__(512, 1)
void lstm_mma(const __nv_bfloat16* __restrict__ Ah0, const __nv_bfloat16* __restrict__ Al0,
              const __nv_bfloat16* __restrict__ Ah1, const __nv_bfloat16* __restrict__ Al1,
              const __nv_bfloat16* __restrict__ Bh_st, const __nv_bfloat16* __restrict__ Bl_st,
              const float* __restrict__ bias, const float* __restrict__ Wih,
              const float* __restrict__ x, int t, int nka,
              float* __restrict__ c,
              __nv_bfloat16* __restrict__ Oh, __nv_bfloat16* __restrict__ Ol) {
    extern __shared__ char smem[];
    unsigned sb = smem_u32(smem);
    const unsigned BSZ = (unsigned)(K * 288);
    int tid = threadIdx.x, lane = tid & 31, wid = tid >> 5;
    int wm = wid & 7, wn = wid >> 3;
    int y = blockIdx.y;

    // ---- B resident load (once) ----
    {
        size_t bbase = (size_t)y * K * 64;
        for (int i = tid; i < K * 8; i += 512) {
            int k = i >> 3, seg = i & 7;
            unsigned d = sb + (unsigned)(k * 144 + seg * 16);
            cp16(d, Bh_st + bbase + (size_t)k * 64 + seg * 8);
            cp16(d + (unsigned)(K * 144), Bl_st + bbase + (size_t)k * 64 + seg * 8);
        }
        CP_COMMIT();
        CP_WAIT0();
    }
    __syncthreads();

    int bkk = ((lane >> 3) & 1) * 8 + (lane & 7);
    unsigned b_col2 = (unsigned)((wn * 32 + (lane >> 4) * 8) * 2);
    float* zs = (float*)(smem + BSZ);

    // epilogue constants (jl fixed per thread)
    int jl = tid & 15;
    int j = y * 16 + jl;
    float b0r = bias[j], b1r = bias[128 + j], b2r = bias[256 + j], b3r = bias[384 + j];
    float w00 = 0.f, w01 = 0.f, w10 = 0.f, w11 = 0.f, w20 = 0.f, w21 = 0.f, w30 = 0.f, w31 = 0.f;
    if (HASX) {
        w00 = Wih[j * 2];           w01 = Wih[j * 2 + 1];
        w10 = Wih[(128 + j) * 2];   w11 = Wih[(128 + j) * 2 + 1];
        w20 = Wih[(256 + j) * 2];   w21 = Wih[(256 + j) * 2 + 1];
        w30 = Wih[(384 + j) * 2];   w31 = Wih[(384 + j) * 2 + 1];
    }

    for (int m = blockIdx.x; m < MT256; m += gridDim.x) {
        int nbase = m * 256;

        // A fragment global offsets (clamped rows)
        size_t offA[2][2];
#pragma unroll
        for (int mt = 0; mt < 2; mt++)
#pragma unroll
            for (int h = 0; h < 2; h++) {
                int gr = nbase + wm * 32 + mt * 16 + h * 8 + (lane >> 2);
                if (gr >= NN) gr = NN - 1;
                offA[mt][h] = (size_t)gr * 128 + 2 * (lane & 3);
            }

        float acc[2][4][4];
#pragma unroll
        for (int mt = 0; mt < 2; mt++)
#pragma unroll
            for (int nf = 0; nf < 4; nf++)
#pragma unroll
                for (int i = 0; i < 4; i++) acc[mt][nf][i] = 0.f;

        unsigned aA[2][4], lA[2][4], aB[2][4], lB[2][4];

        // k-loop: unrolled by 2 with ping-pong A buffers, no barriers.
        if (nka > 0) {
            load_frag(aA, Ah0, offA, 0);
            load_frag(lA, Al0, offA, 0);
        }
        for (int kc = 0; kc < nka; kc += 2) {
            // prefetch kc+1 into B-buffers
            {
                int kn = kc + 1;
                const __nv_bfloat16 *H, *L;
                int ko;
                if (K == 256 && kn >= 8) { H = Ah1; L = Al1; ko = (kn - 8) * 16; }
                else                     { H = Ah0; L = Al0; ko = kn * 16; }
                load_frag(aB, H, offA, ko);
                load_frag(lB, L, offA, ko);
            }
            // compute kc with A-buffers
            {
                unsigned bh[4][2], bl[4][2];
                unsigned bad = sb + (unsigned)((kc * 16 + bkk) * 144) + b_col2;
#pragma unroll
                for (int np = 0; np < 2; np++) {
                    LDSM_X4T(bh[np * 2][0], bh[np * 2][1], bh[np * 2 + 1][0], bh[np * 2 + 1][1],
                             bad + np * 32u);
                    LDSM_X4T(bl[np * 2][0], bl[np * 2][1], bl[np * 2 + 1][0], bl[np * 2 + 1][1],
                             bad + (unsigned)(K * 144) + np * 32u);
                }
#pragma unroll
                for (int mt = 0; mt < 2; mt++)
#pragma unroll
                    for (int nf = 0; nf < 4; nf++) {
                        MMA16816(acc[mt][nf], aA[mt], bh[nf]);
                        MMA16816(acc[mt][nf], lA[mt], bh[nf]);
                        MMA16816(acc[mt][nf], aA[mt], bl[nf]);
                    }
            }
            // prefetch kc+2 into A-buffers
            if (kc + 2 < nka) {
                int kn = kc + 2;
                const __nv_bfloat16 *H, *L;
                int ko;
                if (K == 256 && kn >= 8) { H = Ah1; L = Al1; ko = (kn - 8) * 16; }
                else                     { H = Ah0; L = Al0; ko = kn * 16; }
                load_frag(aA, H, offA, ko);
                load_frag(lA, L, offA, ko);
            }
            // compute kc+1 with B-buffers
            {
                int kc1 = kc + 1;
                unsigned bh[4][2], bl[4][2];
                unsigned bad = sb + (unsigned)((kc1 * 16 + bkk) * 144) + b_col2;
#pragma unroll
                for (int np = 0; np < 2; np++) {
                    LDSM_X4T(bh[np * 2][0], bh[np * 2][1], bh[np * 2 + 1][0], bh[np * 2 + 1][1],
                             bad + np * 32u);
                    LDSM_X4T(bl[np * 2][0], bl[np * 2][1], bl[np * 2 + 1][0], bl[np * 2 + 1][1],
                             bad + (unsigned)(K * 144) + np * 32u);
                }
#pragma unroll
                for (int mt = 0; mt < 2; mt++)
#pragma unroll
                    for (int nf = 0; nf < 4; nf++) {
                        MMA16816(acc[mt][nf], aB[mt], bh[nf]);
                        MMA16816(acc[mt][nf], lB[mt], bh[nf]);
                        MMA16816(acc[mt][nf], aB[mt], bl[nf]);
                    }
            }
        }

        __syncthreads();          // previous epilogue readers done -> stage z
#pragma unroll
        for (int mt = 0; mt < 2; mt++)
#pragma unroll
            for (int nf = 0; nf < 4; nf++) {
                int r0 = wm * 32 + mt * 16 + (lane >> 2);
                int c0 = wn * 32 + nf * 8 + (lane & 3) * 2;
                *(float2*)&zs[r0 * 72 + c0] = make_float2(acc[mt][nf][0], acc[mt][nf][1]);
                *(float2*)&zs[(r0 + 8) * 72 + c0] = make_float2(acc[mt][nf][2], acc[mt][nf][3]);
            }
        __syncthreads();

        // fused gate epilogue: 8 rows/thread (256 rows, 16 jl)
#pragma unroll
        for (int it = 0; it < 8; it++) {
            int rl = it * 32 + (tid >> 4);
            int n = nbase + rl;
            if (n >= NN) continue;
            float4 zv = *(const float4*)&zs[rl * 72 + jl * 4];
            float zi = zv.x + b0r;
            float zf = zv.y + b1r;
            float zg = zv.z + b2r;
            float zo = zv.w + b3r;
            if (HASX) {
                float x0 = x[((size_t)n * TT + t) * 2 + 0];
                float x1 = x[((size_t)n * TT + t) * 2 + 1];
                zi += x0 * w00 + x1 * w01;
                zf += x0 * w10 + x1 * w11;
                zg += x0 * w20 + x1 * w21;
                zo += x0 * w30 + x1 * w31;
            }
            float cn = sigf(zf) * c[(size_t)n * 128 + j] + sigf(zi) * tanhf_(zg);
            c[(size_t)n * 128 + j] = cn;
            float h = sigf(zo) * tanhf_(cn);
            __nv_bfloat16 hh = __float2bfloat16(h);
            Oh[(size_t)n * 128 + j] = hh;
            Ol[(size_t)n * 128 + j] = __float2bfloat16(h - __bfloat162float(hh));
        }
        __syncthreads();
    }
}

// ================= GCN (fp32) =================
__global__ __launch_bounds__(256)
void gcn_gemm(const float* __restrict__ A, const float* __restrict__ W,
              float* __restrict__ out, int relu) {
    __shared__ float As[16][68];
    __shared__ float Bs[16][128];
    int tid = threadIdx.x;
    int ty = tid >> 4, tx = tid & 15;
    int nbase = blockIdx.x * 64;
    float acc[4][8];
#pragma unroll
    for (int i = 0; i < 4; i++)
#pragma unroll
        for (int j = 0; j < 8; j++) acc[i][j] = 0.f;
    int a_row = tid >> 2;
    int a_k4 = (tid & 3) * 4;
    for (int kc = 0; kc < 128; kc += 16) {
        int n = nbase + a_row;
        float4 v = make_float4(0.f, 0.f, 0.f, 0.f);
        if (n < NN) v = *(const float4*)(A + (size_t)n * 128 + kc + a_k4);
        if (relu) {
            v.x = fmaxf(v.x, 0.f); v.y = fmaxf(v.y, 0.f);
            v.z = fmaxf(v.z, 0.f); v.w = fmaxf(v.w, 0.f);
        }
        As[a_k4 + 0][a_row] = v.x; As[a_k4 + 1][a_row] = v.y;
        As[a_k4 + 2][a_row] = v.z; As[a_k4 + 3][a_row] = v.w;
#pragma unroll
        for (int r8 = 0; r8 < 8; r8++) {
            int idx = r8 * 256 + tid;
            int k = idx >> 7, jj = idx & 127;
            Bs[k][jj] = W[(kc + k) * 128 + jj];
        }
        __syncthreads();
#pragma unroll
        for (int k = 0; k < 16; k++) {
            float a[4], b[8];
#pragma unroll
            for (int i = 0; i < 4; i++) a[i] = As[k][ty * 4 + i];
#pragma unroll
            for (int jj = 0; jj < 8; jj++) b[jj] = Bs[k][tx * 8 + jj];
#pragma unroll
            for (int i = 0; i < 4; i++)
#pragma unroll
                for (int jj = 0; jj < 8; jj++) acc[i][jj] = fmaf(a[i], b[jj], acc[i][jj]);
        }
        __syncthreads();
    }
#pragma unroll
    for (int i = 0; i < 4; i++) {
        int n = nbase + ty * 4 + i;
        if (n >= NN) continue;
#pragma unroll
        for (int jj = 0; jj < 8; jj++) out[(size_t)n * 128 + tx * 8 + jj] = acc[i][jj];
    }
}

__global__ void gcn_init(const float* __restrict__ hW, const float* __restrict__ bvec,
                         const float* __restrict__ dinv, float* __restrict__ agg) {
    int idx = blockIdx.x * blockDim.x + threadIdx.x;
    if (idx >= NN * 128) return;
    int n = idx >> 7, jj = idx & 127;
    float di = dinv[n];
    agg[idx] = bvec[jj] + hW[idx] * di * di;
}

__global__ void gcn_agg(const float* __restrict__ hW, const int* __restrict__ src,
                        const int* __restrict__ dst, const float* __restrict__ dinv,
                        float* __restrict__ agg, int E) {
    int gw = (blockIdx.x * blockDim.x + threadIdx.x) >> 5;
    int lane = threadIdx.x & 31;
    if (gw >= E) return;
    int s = src[gw], d = dst[gw];
    float w = dinv[s] * dinv[d];
    float4 v = ((const float4*)(hW + (size_t)s * 128))[lane];
    float* p = agg + (size_t)d * 128 + lane * 4;
    atomicAdd(p + 0, v.x * w);
    atomicAdd(p + 1, v.y * w);
    atomicAdd(p + 2, v.z * w);
    atomicAdd(p + 3, v.w * w);
}

__global__ void gcn_gemm12(const float* __restrict__ A, const float* __restrict__ W2,
                           float* __restrict__ out12) {
    int warp = (blockIdx.x * blockDim.x + threadIdx.x) >> 5;
    int lane = threadIdx.x & 31;
    if (warp >= NN) return;
    float acc[12];
#pragma unroll
    for (int jj = 0; jj < 12; jj++) acc[jj] = 0.f;
    for (int k = lane; k < 128; k += 32) {
        float a = fmaxf(A[(size_t)warp * 128 + k], 0.f);
#pragma unroll
        for (int jj = 0; jj < 12; jj++) acc[jj] = fmaf(a, W2[k * 12 + jj], acc[jj]);
    }
#pragma unroll
    for (int jj = 0; jj < 12; jj++) {
        float v = acc[jj];
#pragma unroll
        for (int o = 16; o; o >>= 1) v += __shfl_down_sync(0xffffffffu, v, o);
        if (lane == 0) out12[(size_t)warp * 12 + jj] = v;
    }
}

__global__ void gcn_init12(const float* __restrict__ hW12, const float* __restrict__ b2,
                           const float* __restrict__ dinv, float* __restrict__ out) {
    int idx = blockIdx.x * blockDim.x + threadIdx.x;
    if (idx >= NN * 12) return;
    int n = idx / 12, jj = idx - n * 12;
    float di = dinv[n];
    out[idx] = b2[jj] + hW12[idx] * di * di;
}

__global__ void gcn_agg12(const float* __restrict__ hW12, const int* __restrict__ src,
                          const int* __restrict__ dst, const float* __restrict__ dinv,
                          float* __restrict__ out, int E) {
    int idx = blockIdx.x * blockDim.x + threadIdx.x;
    int e = idx >> 4;
    int jj = idx & 15;
    if (e >= E || jj >= 12) return;
    int s = src[e], d = dst[e];
    float w = dinv[s] * dinv[d];
    atomicAdd(&out[(size_t)d * 12 + jj], hW12[(size_t)s * 12 + jj] * w);
}

// ================= launch =================
extern "C" void kernel_launch(void* const* d_in, const int* in_sizes, int n_in,
                              void* d_out, int out_size) {
    const float* x    = (const float*)d_in[0];
    const int*   ei   = (const int*)d_in[1];
    const float* Wih0 = (const float*)d_in[2];
    const float* Whh0 = (const float*)d_in[3];
    const float* bih0 = (const float*)d_in[4];
    const float* bhh0 = (const float*)d_in[5];
    const float* Wih1 = (const float*)d_in[6];
    const float* Whh1 = (const float*)d_in[7];
    const float* bih1 = (const float*)d_in[8];
    const float* bhh1 = (const float*)d_in[9];
    const float* W0   = (const float*)d_in[10];
    const float* b0   = (const float*)d_in[11];
    const float* W1   = (const float*)d_in[12];
    const float* b1   = (const float*)d_in[13];
    const float* W2   = (const float*)d_in[14];
    const float* b2   = (const float*)d_in[15];
    float* out = (float*)d_out;

    int E = in_sizes[1] / 2;
    const int* src = ei;
    const int* dst = ei + E;

    float* S;
    cudaGetSymbolAddress((void**)&S, g_scratch);
    float* c0 = S;
    float* c1 = S + (size_t)NH;
    __nv_bfloat16* BF = (__nv_bfloat16*)(S + 2 * (size_t)NH);
    __nv_bfloat16* h0h[2] = { BF + 0 * (size_t)NH, BF + 4 * (size_t)NH };
    __nv_bfloat16* h0l[2] = { BF + 1 * (size_t)NH, BF + 5 * (size_t)NH };
    __nv_bfloat16* h1h[2] = { BF + 2 * (size_t)NH, BF + 6 * (size_t)NH };
    __nv_bfloat16* h1l[2] = { BF + 3 * (size_t)NH, BF + 7 * (size_t)NH };
    float* hfin = S + 6 * (size_t)NH;
    float* hw   = S + 7 * (size_t)NH;
    float* agg  = S + 8 * (size_t)NH;
    float* dinv = S + 9 * (size_t)NH;
    __nv_bfloat16* B0h = (__nv_bfloat16*)(dinv + 65536);
    __nv_bfloat16* B0l = B0h + 65536;
    __nv_bfloat16* B1h = (__nv_bfloat16*)(dinv + 65536 + 65536);
    __nv_bfloat16* B1l = B1h + 131072;
    float* bias0 = dinv + 65536 + 65536 + 131072;
    float* bias1 = bias0 + 512;

    zero_k<<<(2 * NH + 255) / 256, 256>>>(S, 2 * NH);
    prep_all<<<512, 256>>>(bih0, bhh0, bih1, bhh1, Whh0, Wih1, Whh1,
                           B0h, B0l, B1h, B1l, bias0, bias1);

    const int SM0 = 128 * 288 + 73728;   // 110592
    const int SM1 = 256 * 288 + 73728;   // 147456
    cudaFuncSetAttribute(lstm_mma<128, true>,  cudaFuncAttributeMaxDynamicSharedMemorySize, SM0);
    cudaFuncSetAttribute(lstm_mma<256, false>, cudaFuncAttributeMaxDynamicSharedMemorySize, SM1);

    dim3 lg(18, 8);
    int p = 0;
    for (int t = 0; t < TT; t++) {
        lstm_mma<128, true><<<lg, 512, SM0>>>(
            h0h[p], h0l[p], (const __nv_bfloat16*)nullptr, (const __nv_bfloat16*)nullptr,
            B0h, B0l, bias0, Wih0, x, t, t == 0 ? 0 : 8,
            c0, h0h[1 - p], h0l[1 - p]);
        lstm_mma<256, false><<<lg, 512, SM1>>>(
            h0h[1 - p], h0l[1 - p], h1h[p], h1l[p],
            B1h, B1l, bias1, (const float*)nullptr, (const float*)nullptr, 0, t == 0 ? 8 : 16,
            c1, h1h[1 - p], h1l[1 - p]);
        p ^= 1;
    }
    recon_h<<<(NH + 255) / 256, 256>>>(h1h[p], h1l[p], hfin);

    deg_init<<<(NN + 255) / 256, 256>>>(dinv);
    deg_count<<<(E + 255) / 256, 256>>>(dst, dinv, E);
    deg_rsqrt<<<(NN + 255) / 256, 256>>>(dinv);

    gcn_gemm<<<(NN + 63) / 64, 256>>>(hfin, W0, hw, 0);
    gcn_init<<<(NN * 128 + 255) / 256, 256>>>(hw, b0, dinv, agg);
    gcn_agg<<<(E + 7) / 8, 256>>>(hw, src, dst, dinv, agg, E);
    gcn_gemm<<<(NN + 63) / 64, 256>>>(agg, W1, hw, 1);
    gcn_init<<<(NN * 128 + 255) / 256, 256>>>(hw, b1, dinv, agg);
    gcn_agg<<<(E + 7) / 8, 256>>>(hw, src, dst, dinv, agg, E);
    gcn_gemm12<<<(NN * 32 + 255) / 256, 256>>>(agg, W2, hw);
    gcn_init12<<<(NN * 12 + 255) / 256, 256>>>(hw, b2, dinv, out);
    gcn_agg12<<<((size_t)E * 16 + 255) / 256, 256>>>(hw, src, dst, dinv, out, E);
}

// round 10
// speedup vs baseline: 1.4150x; 1.4150x over previous
#include <cuda_runtime.h>
#include <cuda_bf16.h>
#include <math.h>

#define TT   12
#define NN   50000
#define NH   (NN * 128)
#define MT512 98            // ceil(50000/512)

// ================= scratch =================
// floats: c0 c1 (2NH) | h bf16 8xNH (4NH fl) | hfin hw agg (3NH) | dinv 65536 |
// bf16 tail: B0 h/l (2x73728) B1 h/l (2x139264) B1t0 h/l (2x73728)
//            xpad h/l (2x9.6M) ones h/l (2x800K)
__device__ float g_scratch[9 * NH + 65536 + 10700000];

// ================= PTX helpers (portable, sm_80+) =================
__device__ __forceinline__ unsigned smem_u32(const void* p) {
    unsigned a;
    asm("{ .reg .u64 t; cvta.to.shared.u64 t, %1; cvt.u32.u64 %0, t; }" : "=r"(a) : "l"(p));
    return a;
}
__device__ __forceinline__ void cp16(unsigned dst, const void* src) {
    asm volatile("cp.async.cg.shared.global [%0], [%1], 16;" :: "r"(dst), "l"(src));
}
#define CP_COMMIT() asm volatile("cp.async.commit_group;" ::: "memory")
#define CP_WAIT0()  asm volatile("cp.async.wait_group 0;" ::: "memory")
#define CP_WAIT1()  asm volatile("cp.async.wait_group 1;" ::: "memory")

#define LDSM_X4(r0, r1, r2, r3, a) \
    asm volatile("ldmatrix.sync.aligned.m8n8.x4.shared.b16 {%0,%1,%2,%3}, [%4];" \
        : "=r"(r0), "=r"(r1), "=r"(r2), "=r"(r3) : "r"(a))

#define LDSM_X4T(r0, r1, r2, r3, a) \
    asm volatile("ldmatrix.sync.aligned.m8n8.x4.trans.shared.b16 {%0,%1,%2,%3}, [%4];" \
        : "=r"(r0), "=r"(r1), "=r"(r2), "=r"(r3) : "r"(a))

#define MMA16816(d, a, b) \
    asm volatile("mma.sync.aligned.m16n8k16.row.col.f32.bf16.bf16.f32 " \
        "{%0,%1,%2,%3}, {%4,%5,%6,%7}, {%8,%9}, {%0,%1,%2,%3};" \
        : "+f"((d)[0]), "+f"((d)[1]), "+f"((d)[2]), "+f"((d)[3]) \
        : "r"((a)[0]), "r"((a)[1]), "r"((a)[2]), "r"((a)[3]), "r"((b)[0]), "r"((b)[1]))

__device__ __forceinline__ float sigf(float z) { return __fdividef(1.0f, 1.0f + __expf(-z)); }
__device__ __forceinline__ float tanhf_(float z) { return __fdividef(2.0f, 1.0f + __expf(-2.0f * z)) - 1.0f; }

__device__ __forceinline__ void bf16split(float w, __nv_bfloat16* hi, __nv_bfloat16* lo) {
    __nv_bfloat16 h = __float2bfloat16(w);
    *hi = h;
    *lo = __float2bfloat16(w - __bfloat162float(h));
}

// ================= prep kernels =================
__global__ void zero_k(float* p, int n) {
    int i = blockIdx.x * blockDim.x + threadIdx.x;
    if (i < n) p[i] = 0.0f;
}

// xpad[t][n][16] = [x0, x1, 1, 0...]; t==12 slot -> ones[n][16] = [1, 0...]
__global__ void prep_aug(const float* __restrict__ x,
                         __nv_bfloat16* __restrict__ xph, __nv_bfloat16* __restrict__ xpl,
                         __nv_bfloat16* __restrict__ onh, __nv_bfloat16* __restrict__ onl) {
    int idx = blockIdx.x * blockDim.x + threadIdx.x;
    if (idx >= 13 * NN * 16) return;
    int col = idx & 15;
    int rest = idx >> 4;
    int n = rest % NN;
    int t = rest / NN;
    float v = 0.f;
    if (t < 12) {
        if (col < 2) v = x[((size_t)n * TT + t) * 2 + col];
        else if (col == 2) v = 1.0f;
        __nv_bfloat16 hi, lo;
        bf16split(v, &hi, &lo);
        size_t o = ((size_t)t * NN + n) * 16 + col;
        xph[o] = hi; xpl[o] = lo;
    } else {
        if (col == 0) v = 1.0f;
        __nv_bfloat16 hi, lo;
        bf16split(v, &hi, &lo);
        size_t o = (size_t)n * 16 + col;
        onh[o] = hi; onl[o] = lo;
    }
}

// staged B layout: [y(8)][k(BROWS)][col(64)], col = g*16 + jl, ro = g*128 + y*16 + jl
__global__ void prep_B0(const float* __restrict__ Whh0, const float* __restrict__ Wih0,
                        const float* __restrict__ bih0, const float* __restrict__ bhh0,
                        __nv_bfloat16* __restrict__ Bh, __nv_bfloat16* __restrict__ Bl) {
    int idx = blockIdx.x * blockDim.x + threadIdx.x;      // 8*144*64
    if (idx >= 8 * 144 * 64) return;
    int y = idx / (144 * 64);
    int rem = idx - y * (144 * 64);
    int k = rem >> 6, col = rem & 63;
    int ro = (col >> 4) * 128 + y * 16 + (col & 15);
    float w = 0.f;
    if (k < 128) w = Whh0[ro * 128 + k];
    else if (k == 128) w = Wih0[ro * 2 + 0];
    else if (k == 129) w = Wih0[ro * 2 + 1];
    else if (k == 130) w = bih0[ro] + bhh0[ro];
    __nv_bfloat16 hi, lo;
    bf16split(w, &hi, &lo);
    Bh[idx] = hi; Bl[idx] = lo;
}

__global__ void prep_B1(const float* __restrict__ Wih1, const float* __restrict__ Whh1,
                        const float* __restrict__ bih1, const float* __restrict__ bhh1,
                        __nv_bfloat16* __restrict__ Bh, __nv_bfloat16* __restrict__ Bl) {
    int idx = blockIdx.x * blockDim.x + threadIdx.x;      // 8*272*64
    if (idx >= 8 * 272 * 64) return;
    int y = idx / (272 * 64);
    int rem = idx - y * (272 * 64);
    int k = rem >> 6, col = rem & 63;
    int ro = (col >> 4) * 128 + y * 16 + (col & 15);
    float w = 0.f;
    if (k < 128) w = Wih1[ro * 128 + k];
    else if (k < 256) w = Whh1[ro * 128 + (k - 128)];
    else if (k == 256) w = bih1[ro] + bhh1[ro];
    __nv_bfloat16 hi, lo;
    bf16split(w, &hi, &lo);
    Bh[idx] = hi; Bl[idx] = lo;
}

__global__ void prep_B1t0(const float* __restrict__ Wih1,
                          const float* __restrict__ bih1, const float* __restrict__ bhh1,
                          __nv_bfloat16* __restrict__ Bh, __nv_bfloat16* __restrict__ Bl) {
    int idx = blockIdx.x * blockDim.x + threadIdx.x;      // 8*144*64
    if (idx >= 8 * 144 * 64) return;
    int y = idx / (144 * 64);
    int rem = idx - y * (144 * 64);
    int k = rem >> 6, col = rem & 63;
    int ro = (col >> 4) * 128 + y * 16 + (col & 15);
    float w = 0.f;
    if (k < 128) w = Wih1[ro * 128 + k];
    else if (k == 128) w = bih1[ro] + bhh1[ro];
    __nv_bfloat16 hi, lo;
    bf16split(w, &hi, &lo);
    Bh[idx] = hi; Bl[idx] = lo;
}

__global__ void deg_init(float* deg) {
    int i = blockIdx.x * blockDim.x + threadIdx.x;
    if (i < NN) deg[i] = 1.0f;
}
__global__ void deg_count(const int* __restrict__ dst, float* deg, int E) {
    int i = blockIdx.x * blockDim.x + threadIdx.x;
    if (i < E) atomicAdd(&deg[dst[i]], 1.0f);
}
__global__ void deg_rsqrt(float* deg) {
    int i = blockIdx.x * blockDim.x + threadIdx.x;
    if (i < NN) deg[i] = rsqrtf(deg[i]);
}

__global__ void recon_h(const __nv_bfloat16* __restrict__ hh, const __nv_bfloat16* __restrict__ hl,
                        float* __restrict__ out) {
    int i = blockIdx.x * blockDim.x + threadIdx.x;
    if (i < NH) out[i] = __bfloat162float(hh[i]) + __bfloat162float(hl[i]);
}

// ================= LSTM step: 16 m-warps x 64 cols, zero m-loop barriers =================
// grid (18, 8). Block: 512 thr = 16 warps, each warp owns 32 rows; m-tile 512 rows.
// B resident smem [k][64] stride 144B (hi | lo at +BROWS*144).
// A: warp-private 2-stage cp.async ring (stage 3072B: hi 1536 | lo 1536, rows stride 48B).
// Aug columns fold x-term and bias into the GEMM. Epilogue fully in registers.
template <int NK>
__global__ __launch_bounds__(512, 1)
void lstm_mma(const __nv_bfloat16* __restrict__ A0h, const __nv_bfloat16* __restrict__ A0l,
              const __nv_bfloat16* __restrict__ A1h, const __nv_bfloat16* __restrict__ A1l,
              const __nv_bfloat16* __restrict__ AGh, const __nv_bfloat16* __restrict__ AGl,
              const __nv_bfloat16* __restrict__ Bh_st, const __nv_bfloat16* __restrict__ Bl_st,
              int kstart,
              float* __restrict__ c,
              __nv_bfloat16* __restrict__ Oh, __nv_bfloat16* __restrict__ Ol) {
    extern __shared__ char smem[];
    unsigned sb = smem_u32(smem);
    const int BROWS = NK * 16;
    const unsigned BSZ = (unsigned)(BROWS * 288);       // hi + lo
    int tid = threadIdx.x, lane = tid & 31, wid = tid >> 5;
    int y = blockIdx.y;

    // ---- B resident load (once) ----
    {
        size_t bbase = (size_t)y * BROWS * 64;
        for (int i = tid; i < BROWS * 8; i += 512) {
            int k = i >> 3, seg = i & 7;
            unsigned d = sb + (unsigned)(k * 144 + seg * 16);
            cp16(d, Bh_st + bbase + (size_t)k * 64 + seg * 8);
            cp16(d + (unsigned)(BROWS * 144), Bl_st + bbase + (size_t)k * 64 + seg * 8);
        }
        CP_COMMIT();
        CP_WAIT0();
    }
    __syncthreads();

    unsigned ring = sb + BSZ + (unsigned)wid * 6144u;   // 2 stages x 3072B
    unsigned a_ad[2];
#pragma unroll
    for (int mt = 0; mt < 2; mt++)
        a_ad[mt] = (unsigned)((mt * 16 + (lane & 15)) * 48 + (lane >> 4) * 16);
    int bkk = ((lane >> 3) & 1) * 8 + (lane & 7);
    unsigned bcol8 = (unsigned)((lane >> 4) * 8 * 2);

    int q = lane & 3;

    for (int m = blockIdx.x; m < MT512; m += gridDim.x) {
        int nbase = m * 512;
        int arow = nbase + wid * 32 + lane;
        if (arow >= NN) arow = NN - 1;

        // A-chunk loader: kn -> source select
        auto loadA = [&](int kn) {
            const __nv_bfloat16 *H, *L;
            size_t so;
            if (kn < 8)                    { H = A0h; L = A0l; so = (size_t)arow * 128 + kn * 16; }
            else if (NK == 17 && kn < 16)  { H = A1h; L = A1l; so = (size_t)arow * 128 + (kn - 8) * 16; }
            else                           { H = AGh; L = AGl; so = (size_t)arow * 16; }
            unsigned d = ring + (unsigned)((kn & 1) * 3072 + lane * 48);
            cp16(d,         H + so);
            cp16(d + 16u,   H + so + 8);
            cp16(d + 1536u, L + so);
            cp16(d + 1552u, L + so + 8);
            CP_COMMIT();
        };

        float acc[2][8][4];
#pragma unroll
        for (int mt = 0; mt < 2; mt++)
#pragma unroll
            for (int nf = 0; nf < 8; nf++)
#pragma unroll
                for (int i = 0; i < 4; i++) acc[mt][nf][i] = 0.f;

        loadA(kstart);
        for (int kc = kstart; kc < NK; kc++) {
            if (kc + 1 < NK) { loadA(kc + 1); CP_WAIT1(); }
            else             { CP_WAIT0(); }

            unsigned abuf = ring + (unsigned)((kc & 1) * 3072);
            unsigned ah[2][4], al[2][4];
#pragma unroll
            for (int mt = 0; mt < 2; mt++) {
                LDSM_X4(ah[mt][0], ah[mt][1], ah[mt][2], ah[mt][3], abuf + a_ad[mt]);
                LDSM_X4(al[mt][0], al[mt][1], al[mt][2], al[mt][3], abuf + 1536u + a_ad[mt]);
            }
            unsigned bbase_k = sb + (unsigned)((kc * 16 + bkk) * 144);
#pragma unroll
            for (int half = 0; half < 2; half++) {
                unsigned bh[4][2], bl[4][2];
#pragma unroll
                for (int np = 0; np < 2; np++) {
                    unsigned ad = bbase_k + (unsigned)(half * 64 + np * 32) + bcol8;
                    LDSM_X4T(bh[np * 2][0], bh[np * 2][1], bh[np * 2 + 1][0], bh[np * 2 + 1][1], ad);
                    LDSM_X4T(bl[np * 2][0], bl[np * 2][1], bl[np * 2 + 1][0], bl[np * 2 + 1][1],
                             ad + (unsigned)(BROWS * 144));
                }
#pragma unroll
                for (int mt = 0; mt < 2; mt++)
#pragma unroll
                    for (int nf4 = 0; nf4 < 4; nf4++) {
                        int nf = half * 4 + nf4;
                        MMA16816(acc[mt][nf], ah[mt], bh[nf4]);
                        MMA16816(acc[mt][nf], al[mt], bh[nf4]);
                        MMA16816(acc[mt][nf], ah[mt], bl[nf4]);
                    }
            }
        }

        // ---- in-register epilogue: col = g*16 + jl, all 4 gates local ----
#pragma unroll
        for (int mt = 0; mt < 2; mt++)
#pragma unroll
            for (int rp = 0; rp < 2; rp++) {
                int n = nbase + wid * 32 + mt * 16 + rp * 8 + (lane >> 2);
                if (n >= NN) continue;
#pragma unroll
                for (int jli = 0; jli < 4; jli++) {
                    int jh = jli >> 1;                   // j half (0: jl<8, 1: jl>=8)
                    int par = jli & 1;                   // col parity
                    int jl = q * 2 + par + jh * 8;
                    int ridx = rp * 2 + par;
                    float zi = acc[mt][0 + jh][ridx];
                    float zf = acc[mt][2 + jh][ridx];
                    float zg = acc[mt][4 + jh][ridx];
                    float zo = acc[mt][6 + jh][ridx];
                    int j = y * 16 + jl;
                    size_t o = (size_t)n * 128 + j;
                    float cn = sigf(zf) * c[o] + sigf(zi) * tanhf_(zg);
                    c[o] = cn;
                    float h = sigf(zo) * tanhf_(cn);
                    __nv_bfloat16 hh = __float2bfloat16(h);
                    Oh[o] = hh;
                    Ol[o] = __float2bfloat16(h - __bfloat162float(hh));
                }
            }
        // no __syncthreads: ring warp-private, B read-only, epilogue register-local
    }
}

// ================= GCN (fp32, proven) =================
__global__ __launch_bounds__(256)
void gcn_gemm(const float* __restrict__ A, const float* __restrict__ W,
              float* __restrict__ out, int relu) {
    __shared__ float As[16][68];
    __shared__ float Bs[16][128];
    int tid = threadIdx.x;
    int ty = tid >> 4, tx = tid & 15;
    int nbase = blockIdx.x * 64;
    float acc[4][8];
#pragma unroll
    for (int i = 0; i < 4; i++)
#pragma unroll
        for (int j = 0; j < 8; j++) acc[i][j] = 0.f;
    int a_row = tid >> 2;
    int a_k4 = (tid & 3) * 4;
    for (int kc = 0; kc < 128; kc += 16) {
        int n = nbase + a_row;
        float4 v = make_float4(0.f, 0.f, 0.f, 0.f);
        if (n < NN) v = *(const float4*)(A + (size_t)n * 128 + kc + a_k4);
        if (relu) {
            v.x = fmaxf(v.x, 0.f); v.y = fmaxf(v.y, 0.f);
            v.z = fmaxf(v.z, 0.f); v.w = fmaxf(v.w, 0.f);
        }
        As[a_k4 + 0][a_row] = v.x; As[a_k4 + 1][a_row] = v.y;
        As[a_k4 + 2][a_row] = v.z; As[a_k4 + 3][a_row] = v.w;
#pragma unroll
        for (int r8 = 0; r8 < 8; r8++) {
            int idx = r8 * 256 + tid;
            int k = idx >> 7, jj = idx & 127;
            Bs[k][jj] = W[(kc + k) * 128 + jj];
        }
        __syncthreads();
#pragma unroll
        for (int k = 0; k < 16; k++) {
            float a[4], b[8];
#pragma unroll
            for (int i = 0; i < 4; i++) a[i] = As[k][ty * 4 + i];
#pragma unroll
            for (int jj = 0; jj < 8; jj++) b[jj] = Bs[k][tx * 8 + jj];
#pragma unroll
            for (int i = 0; i < 4; i++)
#pragma unroll
                for (int jj = 0; jj < 8; jj++) acc[i][jj] = fmaf(a[i], b[jj], acc[i][jj]);
        }
        __syncthreads();
    }
#pragma unroll
    for (int i = 0; i < 4; i++) {
        int n = nbase + ty * 4 + i;
        if (n >= NN) continue;
#pragma unroll
        for (int jj = 0; jj < 8; jj++) out[(size_t)n * 128 + tx * 8 + jj] = acc[i][jj];
    }
}

__global__ void gcn_init(const float* __restrict__ hW, const float* __restrict__ bvec,
                         const float* __restrict__ dinv, float* __restrict__ agg) {
    int idx = blockIdx.x * blockDim.x + threadIdx.x;
    if (idx >= NN * 128) return;
    int n = idx >> 7, jj = idx & 127;
    float di = dinv[n];
    agg[idx] = bvec[jj] + hW[idx] * di * di;
}

__global__ void gcn_agg(const float* __restrict__ hW, const int* __restrict__ src,
                        const int* __restrict__ dst, const float* __restrict__ dinv,
                        float* __restrict__ agg, int E) {
    int gw = (blockIdx.x * blockDim.x + threadIdx.x) >> 5;
    int lane = threadIdx.x & 31;
    if (gw >= E) return;
    int s = src[gw], d = dst[gw];
    float w = dinv[s] * dinv[d];
    float4 v = ((const float4*)(hW + (size_t)s * 128))[lane];
    float* p = agg + (size_t)d * 128 + lane * 4;
    atomicAdd(p + 0, v.x * w);
    atomicAdd(p + 1, v.y * w);
    atomicAdd(p + 2, v.z * w);
    atomicAdd(p + 3, v.w * w);
}

__global__ void gcn_gemm12(const float* __restrict__ A, const float* __restrict__ W2,
                           float* __restrict__ out12) {
    int warp = (blockIdx.x * blockDim.x + threadIdx.x) >> 5;
    int lane = threadIdx.x & 31;
    if (warp >= NN) return;
    float acc[12];
#pragma unroll
    for (int jj = 0; jj < 12; jj++) acc[jj] = 0.f;
    for (int k = lane; k < 128; k += 32) {
        float a = fmaxf(A[(size_t)warp * 128 + k], 0.f);
#pragma unroll
        for (int jj = 0; jj < 12; jj++) acc[jj] = fmaf(a, W2[k * 12 + jj], acc[jj]);
    }
#pragma unroll
    for (int jj = 0; jj < 12; jj++) {
        float v = acc[jj];
#pragma unroll
        for (int o = 16; o; o >>= 1) v += __shfl_down_sync(0xffffffffu, v, o);
        if (lane == 0) out12[(size_t)warp * 12 + jj] = v;
    }
}

__global__ void gcn_init12(const float* __restrict__ hW12, const float* __restrict__ b2,
                           const float* __restrict__ dinv, float* __restrict__ out) {
    int idx = blockIdx.x * blockDim.x + threadIdx.x;
    if (idx >= NN * 12) return;
    int n = idx / 12, jj = idx - n * 12;
    float di = dinv[n];
    out[idx] = b2[jj] + hW12[idx] * di * di;
}

__global__ void gcn_agg12(const float* __restrict__ hW12, const int* __restrict__ src,
                          const int* __restrict__ dst, const float* __restrict__ dinv,
                          float* __restrict__ out, int E) {
    int idx = blockIdx.x * blockDim.x + threadIdx.x;
    int e = idx >> 4;
    int jj = idx & 15;
    if (e >= E || jj >= 12) return;
    int s = src[e], d = dst[e];
    float w = dinv[s] * dinv[d];
    atomicAdd(&out[(size_t)d * 12 + jj], hW12[(size_t)s * 12 + jj] * w);
}

// ================= launch =================
extern "C" void kernel_launch(void* const* d_in, const int* in_sizes, int n_in,
                              void* d_out, int out_size) {
    const float* x    = (const float*)d_in[0];
    const int*   ei   = (const int*)d_in[1];
    const float* Wih0 = (const float*)d_in[2];
    const float* Whh0 = (const float*)d_in[3];
    const float* bih0 = (const float*)d_in[4];
    const float* bhh0 = (const float*)d_in[5];
    const float* Wih1 = (const float*)d_in[6];
    const float* Whh1 = (const float*)d_in[7];
    const float* bih1 = (const float*)d_in[8];
    const float* bhh1 = (const float*)d_in[9];
    const float* W0   = (const float*)d_in[10];
    const float* b0   = (const float*)d_in[11];
    const float* W1   = (const float*)d_in[12];
    const float* b1   = (const float*)d_in[13];
    const float* W2   = (const float*)d_in[14];
    const float* b2   = (const float*)d_in[15];
    float* out = (float*)d_out;

    int E = in_sizes[1] / 2;
    const int* src = ei;
    const int* dst = ei + E;

    float* S;
    cudaGetSymbolAddress((void**)&S, g_scratch);
    float* c0 = S;
    float* c1 = S + (size_t)NH;
    __nv_bfloat16* BF = (__nv_bfloat16*)(S + 2 * (size_t)NH);
    __nv_bfloat16* h0h[2] = { BF + 0 * (size_t)NH, BF + 4 * (size_t)NH };
    __nv_bfloat16* h0l[2] = { BF + 1 * (size_t)NH, BF + 5 * (size_t)NH };
    __nv_bfloat16* h1h[2] = { BF + 2 * (size_t)NH, BF + 6 * (size_t)NH };
    __nv_bfloat16* h1l[2] = { BF + 3 * (size_t)NH, BF + 7 * (size_t)NH };
    float* hfin = S + 6 * (size_t)NH;
    float* hw   = S + 7 * (size_t)NH;
    float* agg  = S + 8 * (size_t)NH;
    float* dinv = S + 9 * (size_t)NH;
    __nv_bfloat16* Q = (__nv_bfloat16*)(dinv + 65536);
    __nv_bfloat16* B0h   = Q;                 Q += 8 * 144 * 64;
    __nv_bfloat16* B0l   = Q;                 Q += 8 * 144 * 64;
    __nv_bfloat16* B1h   = Q;                 Q += 8 * 272 * 64;
    __nv_bfloat16* B1l   = Q;                 Q += 8 * 272 * 64;
    __nv_bfloat16* Bt0h  = Q;                 Q += 8 * 144 * 64;
    __nv_bfloat16* Bt0l  = Q;                 Q += 8 * 144 * 64;
    __nv_bfloat16* xph   = Q;                 Q += (size_t)12 * NN * 16;
    __nv_bfloat16* xpl   = Q;                 Q += (size_t)12 * NN * 16;
    __nv_bfloat16* onh   = Q;                 Q += (size_t)NN * 16;
    __nv_bfloat16* onl   = Q;                 Q += (size_t)NN * 16;

    zero_k<<<(2 * NH + 255) / 256, 256>>>(S, 2 * NH);
    prep_aug<<<(13 * NN * 16 + 255) / 256, 256>>>(x, xph, xpl, onh, onl);
    prep_B0<<<(8 * 144 * 64 + 255) / 256, 256>>>(Whh0, Wih0, bih0, bhh0, B0h, B0l);
    prep_B1<<<(8 * 272 * 64 + 255) / 256, 256>>>(Wih1, Whh1, bih1, bhh1, B1h, B1l);
    prep_B1t0<<<(8 * 144 * 64 + 255) / 256, 256>>>(Wih1, bih1, bhh1, Bt0h, Bt0l);

    const int SM9  = 144 * 288 + 16 * 6144;   // 41472 + 98304 = 139776
    const int SM17 = 272 * 288 + 16 * 6144;   // 78336 + 98304 = 176640
    cudaFuncSetAttribute(lstm_mma<9>,  cudaFuncAttributeMaxDynamicSharedMemorySize, SM9);
    cudaFuncSetAttribute(lstm_mma<17>, cudaFuncAttributeMaxDynamicSharedMemorySize, SM17);

    dim3 lg(18, 8);
    int p = 0;
    for (int t = 0; t < TT; t++) {
        // layer 0: A = [h0 | xpad_t]; t=0 skips the h0 part (h0=0)
        lstm_mma<9><<<lg, 512, SM9>>>(
            h0h[p], h0l[p], (const __nv_bfloat16*)nullptr, (const __nv_bfloat16*)nullptr,
            xph + (size_t)t * NN * 16, xpl + (size_t)t * NN * 16,
            B0h, B0l, t == 0 ? 8 : 0, c0, h0h[1 - p], h0l[1 - p]);
        // layer 1
        if (t == 0) {
            lstm_mma<9><<<lg, 512, SM9>>>(
                h0h[1 - p], h0l[1 - p], (const __nv_bfloat16*)nullptr, (const __nv_bfloat16*)nullptr,
                onh, onl, Bt0h, Bt0l, 0, c1, h1h[1 - p], h1l[1 - p]);
        } else {
            lstm_mma<17><<<lg, 512, SM17>>>(
                h0h[1 - p], h0l[1 - p], h1h[p], h1l[p],
                onh, onl, B1h, B1l, 0, c1, h1h[1 - p], h1l[1 - p]);
        }
        p ^= 1;
    }
    recon_h<<<(NH + 255) / 256, 256>>>(h1h[p], h1l[p], hfin);

    deg_init<<<(NN + 255) / 256, 256>>>(dinv);
    deg_count<<<(E + 255) / 256, 256>>>(dst, dinv, E);
    deg_rsqrt<<<(NN + 255) / 256, 256>>>(dinv);

    gcn_gemm<<<(NN + 63) / 64, 256>>>(hfin, W0, hw, 0);
    gcn_init<<<(NN * 128 + 255) / 256, 256>>>(hw, b0, dinv, agg);
    gcn_agg<<<(E + 7) / 8, 256>>>(hw, src, dst, dinv, agg, E);
    gcn_gemm<<<(NN + 63) / 64, 256>>>(agg, W1, hw, 1);
    gcn_init<<<(NN * 128 + 255) / 256, 256>>>(hw, b1, dinv, agg);
    gcn_agg<<<(E + 7) / 8, 256>>>(hw, src, dst, dinv, agg, E);
    gcn_gemm12<<<(NN * 32 + 255) / 256, 256>>>(agg, W2, hw);
    gcn_init12<<<(NN * 12 + 255) / 256, 256>>>(hw, b2, dinv, out);
    gcn_agg12<<<((size_t)E * 16 + 255) / 256, 256>>>(hw, src, dst, dinv, out, E);
}

// round 13
// speedup vs baseline: 2.1739x; 1.5364x over previous
#include <cuda_runtime.h>
#include <cuda_fp16.h>
#include <math.h>

#define TT   12
#define NN   50000
#define NH   (NN * 128)
#define MT512 98            // ceil(50000/512)

// ================= scratch =================
// floats: c0 c1 (2NH) | h fp16 4 bufs (2NH fl) | hfin hw agg (3NH) | dinv 65536 |
// half tail: B0 (8*144*64) B1 (8*272*64) Bt0 (8*144*64) xpad (12*NN*16) ones (NN*16)
__device__ float g_scratch[7 * NH + 65536 + 5400000];

// ================= PTX helpers (portable, sm_80+) =================
__device__ __forceinline__ unsigned smem_u32(const void* p) {
    unsigned a;
    asm("{ .reg .u64 t; cvta.to.shared.u64 t, %1; cvt.u32.u64 %0, t; }" : "=r"(a) : "l"(p));
    return a;
}
__device__ __forceinline__ void cp16(unsigned dst, const void* src) {
    asm volatile("cp.async.cg.shared.global [%0], [%1], 16;" :: "r"(dst), "l"(src));
}
#define CP_COMMIT() asm volatile("cp.async.commit_group;" ::: "memory")
#define CP_WAIT0()  asm volatile("cp.async.wait_group 0;" ::: "memory")
#define CP_WAIT1()  asm volatile("cp.async.wait_group 1;" ::: "memory")

#define LDSM_X4(r0, r1, r2, r3, a) \
    asm volatile("ldmatrix.sync.aligned.m8n8.x4.shared.b16 {%0,%1,%2,%3}, [%4];" \
        : "=r"(r0), "=r"(r1), "=r"(r2), "=r"(r3) : "r"(a))

#define LDSM_X4T(r0, r1, r2, r3, a) \
    asm volatile("ldmatrix.sync.aligned.m8n8.x4.trans.shared.b16 {%0,%1,%2,%3}, [%4];" \
        : "=r"(r0), "=r"(r1), "=r"(r2), "=r"(r3) : "r"(a))

#define MMA16816F16(d, a, b) \
    asm volatile("mma.sync.aligned.m16n8k16.row.col.f32.f16.f16.f32 " \
        "{%0,%1,%2,%3}, {%4,%5,%6,%7}, {%8,%9}, {%0,%1,%2,%3};" \
        : "+f"((d)[0]), "+f"((d)[1]), "+f"((d)[2]), "+f"((d)[3]) \
        : "r"((a)[0]), "r"((a)[1]), "r"((a)[2]), "r"((a)[3]), "r"((b)[0]), "r"((b)[1]))

__device__ __forceinline__ float sigf(float z) { return __fdividef(1.0f, 1.0f + __expf(-z)); }
__device__ __forceinline__ float tanhf_(float z) { return __fdividef(2.0f, 1.0f + __expf(-2.0f * z)) - 1.0f; }

// ================= prep kernels =================
__global__ void zero_k(float* p, int n) {
    int i = blockIdx.x * blockDim.x + threadIdx.x;
    if (i < n) p[i] = 0.0f;
}

// xpad[t][n][16] = [x0, x1, 1, 0...]; t==12 slot -> ones[n][16] = [1, 0...]
__global__ void prep_aug(const float* __restrict__ x,
                         __half* __restrict__ xp, __half* __restrict__ on) {
    int idx = blockIdx.x * blockDim.x + threadIdx.x;
    if (idx >= 13 * NN * 16) return;
    int col = idx & 15;
    int rest = idx >> 4;
    int n = rest % NN;
    int t = rest / NN;
    float v = 0.f;
    if (t < 12) {
        if (col < 2) v = x[((size_t)n * TT + t) * 2 + col];
        else if (col == 2) v = 1.0f;
        xp[((size_t)t * NN + n) * 16 + col] = __float2half(v);
    } else {
        if (col == 0) v = 1.0f;
        on[(size_t)n * 16 + col] = __float2half(v);
    }
}

// staged B layout: [y(8)][k(BROWS)][col(64)], col = g*16 + jl, ro = g*128 + y*16 + jl
__global__ void prep_B0(const float* __restrict__ Whh0, const float* __restrict__ Wih0,
                        const float* __restrict__ bih0, const float* __restrict__ bhh0,
                        __half* __restrict__ B) {
    int idx = blockIdx.x * blockDim.x + threadIdx.x;      // 8*144*64
    if (idx >= 8 * 144 * 64) return;
    int y = idx / (144 * 64);
    int rem = idx - y * (144 * 64);
    int k = rem >> 6, col = rem & 63;
    int ro = (col >> 4) * 128 + y * 16 + (col & 15);
    float w = 0.f;
    if (k < 128) w = Whh0[ro * 128 + k];
    else if (k == 128) w = Wih0[ro * 2 + 0];
    else if (k == 129) w = Wih0[ro * 2 + 1];
    else if (k == 130) w = bih0[ro] + bhh0[ro];
    B[idx] = __float2half(w);
}

__global__ void prep_B1(const float* __restrict__ Wih1, const float* __restrict__ Whh1,
                        const float* __restrict__ bih1, const float* __restrict__ bhh1,
                        __half* __restrict__ B) {
    int idx = blockIdx.x * blockDim.x + threadIdx.x;      // 8*272*64
    if (idx >= 8 * 272 * 64) return;
    int y = idx / (272 * 64);
    int rem = idx - y * (272 * 64);
    int k = rem >> 6, col = rem & 63;
    int ro = (col >> 4) * 128 + y * 16 + (col & 15);
    float w = 0.f;
    if (k < 128) w = Wih1[ro * 128 + k];
    else if (k < 256) w = Whh1[ro * 128 + (k - 128)];
    else if (k == 256) w = bih1[ro] + bhh1[ro];
    B[idx] = __float2half(w);
}

__global__ void prep_B1t0(const float* __restrict__ Wih1,
                          const float* __restrict__ bih1, const float* __restrict__ bhh1,
                          __half* __restrict__ B) {
    int idx = blockIdx.x * blockDim.x + threadIdx.x;      // 8*144*64
    if (idx >= 8 * 144 * 64) return;
    int y = idx / (144 * 64);
    int rem = idx - y * (144 * 64);
    int k = rem >> 6, col = rem & 63;
    int ro = (col >> 4) * 128 + y * 16 + (col & 15);
    float w = 0.f;
    if (k < 128) w = Wih1[ro * 128 + k];
    else if (k == 128) w = bih1[ro] + bhh1[ro];
    B[idx] = __float2half(w);
}

__global__ void deg_init(float* deg) {
    int i = blockIdx.x * blockDim.x + threadIdx.x;
    if (i < NN) deg[i] = 1.0f;
}
__global__ void deg_count(const int* __restrict__ dst, float* deg, int E) {
    int i = blockIdx.x * blockDim.x + threadIdx.x;
    if (i < E) atomicAdd(&deg[dst[i]], 1.0f);
}
__global__ void deg_rsqrt(float* deg) {
    int i = blockIdx.x * blockDim.x + threadIdx.x;
    if (i < NN) deg[i] = rsqrtf(deg[i]);
}

__global__ void recon_h(const __half* __restrict__ hh, float* __restrict__ out) {
    int i = blockIdx.x * blockDim.x + threadIdx.x;
    if (i < NH) out[i] = __half2float(hh[i]);
}

// ================= LSTM step: fp16 single chain, 16 m-warps x 64 cols =================
// grid (18, 8). 512 thr = 16 warps, 32 rows/warp; m-tile 512 rows. Zero m-loop barriers.
// B resident smem [k][64] stride 144B (fp16). A: warp-private 2-stage cp.async ring
// (stage 1536B, rows stride 48B). Aug columns fold x and bias into the GEMM.
template <int NK>
__global__ __launch_bounds__(512, 1)
void lstm_mma(const __half* __restrict__ A0, const __half* __restrict__ A1,
              const __half* __restrict__ AG,
              const __half* __restrict__ B_st,
              int kstart,
              float* __restrict__ c,
              __half* __restrict__ Oh) {
    extern __shared__ char smem[];
    unsigned sb = smem_u32(smem);
    const int BROWS = NK * 16;
    const unsigned BSZ = (unsigned)(BROWS * 144);
    int tid = threadIdx.x, lane = tid & 31, wid = tid >> 5;
    int y = blockIdx.y;

    // ---- B resident load (once) ----
    {
        size_t bbase = (size_t)y * BROWS * 64;
        for (int i = tid; i < BROWS * 8; i += 512) {
            int k = i >> 3, seg = i & 7;
            cp16(sb + (unsigned)(k * 144 + seg * 16),
                 B_st + bbase + (size_t)k * 64 + seg * 8);
        }
        CP_COMMIT();
        CP_WAIT0();
    }
    __syncthreads();

    unsigned ring = sb + BSZ + (unsigned)wid * 3072u;   // 2 stages x 1536B
    unsigned a_ad[2];
#pragma unroll
    for (int mt = 0; mt < 2; mt++)
        a_ad[mt] = (unsigned)((mt * 16 + (lane & 15)) * 48 + (lane >> 4) * 16);
    int bkk = ((lane >> 3) & 1) * 8 + (lane & 7);
    unsigned bcol8 = (unsigned)((lane >> 4) * 8 * 2);

    int q = lane & 3;

    for (int m = blockIdx.x; m < MT512; m += gridDim.x) {
        int nbase = m * 512;
        int arow = nbase + wid * 32 + lane;
        if (arow >= NN) arow = NN - 1;

        auto loadA = [&](int kn) {
            const __half* H;
            size_t so;
            if (kn < 8)                   { H = A0; so = (size_t)arow * 128 + kn * 16; }
            else if (NK == 17 && kn < 16) { H = A1; so = (size_t)arow * 128 + (kn - 8) * 16; }
            else                          { H = AG; so = (size_t)arow * 16; }
            unsigned d = ring + (unsigned)((kn & 1) * 1536 + lane * 48);
            cp16(d,       H + so);
            cp16(d + 16u, H + so + 8);
            CP_COMMIT();
        };

        float acc[2][8][4];
#pragma unroll
        for (int mt = 0; mt < 2; mt++)
#pragma unroll
            for (int nf = 0; nf < 8; nf++)
#pragma unroll
                for (int i = 0; i < 4; i++) acc[mt][nf][i] = 0.f;

        loadA(kstart);
        for (int kc = kstart; kc < NK; kc++) {
            if (kc + 1 < NK) { loadA(kc + 1); CP_WAIT1(); }
            else             { CP_WAIT0(); }

            unsigned abuf = ring + (unsigned)((kc & 1) * 1536);
            unsigned ah[2][4];
#pragma unroll
            for (int mt = 0; mt < 2; mt++)
                LDSM_X4(ah[mt][0], ah[mt][1], ah[mt][2], ah[mt][3], abuf + a_ad[mt]);

            unsigned bbase_k = sb + (unsigned)((kc * 16 + bkk) * 144);
#pragma unroll
            for (int half = 0; half < 2; half++) {
                unsigned bh[4][2];
#pragma unroll
                for (int np = 0; np < 2; np++) {
                    unsigned ad = bbase_k + (unsigned)(half * 64 + np * 32) + bcol8;
                    LDSM_X4T(bh[np * 2][0], bh[np * 2][1], bh[np * 2 + 1][0], bh[np * 2 + 1][1], ad);
                }
#pragma unroll
                for (int mt = 0; mt < 2; mt++)
#pragma unroll
                    for (int nf4 = 0; nf4 < 4; nf4++)
                        MMA16816F16(acc[mt][half * 4 + nf4], ah[mt], bh[nf4]);
            }
        }

        // ---- in-register epilogue: col = g*16 + jl, all 4 gates local ----
#pragma unroll
        for (int mt = 0; mt < 2; mt++)
#pragma unroll
            for (int rp = 0; rp < 2; rp++) {
                int n = nbase + wid * 32 + mt * 16 + rp * 8 + (lane >> 2);
                if (n >= NN) continue;
#pragma unroll
                for (int jli = 0; jli < 4; jli++) {
                    int jh = jli >> 1;
                    int par = jli & 1;
                    int jl = q * 2 + par + jh * 8;
                    int ridx = rp * 2 + par;
                    float zi = acc[mt][0 + jh][ridx];
                    float zf = acc[mt][2 + jh][ridx];
                    float zg = acc[mt][4 + jh][ridx];
                    float zo = acc[mt][6 + jh][ridx];
                    int j = y * 16 + jl;
                    size_t o = (size_t)n * 128 + j;
                    float cn = sigf(zf) * c[o] + sigf(zi) * tanhf_(zg);
                    c[o] = cn;
                    Oh[o] = __float2half(sigf(zo) * tanhf_(cn));
                }
            }
        // no __syncthreads: ring warp-private, B read-only, epilogue register-local
    }
}

// ================= GCN (fp32, proven) =================
__global__ __launch_bounds__(256)
void gcn_gemm(const float* __restrict__ A, const float* __restrict__ W,
              float* __restrict__ out, int relu) {
    __shared__ float As[16][68];
    __shared__ float Bs[16][128];
    int tid = threadIdx.x;
    int ty = tid >> 4, tx = tid & 15;
    int nbase = blockIdx.x * 64;
    float acc[4][8];
#pragma unroll
    for (int i = 0; i < 4; i++)
#pragma unroll
        for (int j = 0; j < 8; j++) acc[i][j] = 0.f;
    int a_row = tid >> 2;
    int a_k4 = (tid & 3) * 4;
    for (int kc = 0; kc < 128; kc += 16) {
        int n = nbase + a_row;
        float4 v = make_float4(0.f, 0.f, 0.f, 0.f);
        if (n < NN) v = *(const float4*)(A + (size_t)n * 128 + kc + a_k4);
        if (relu) {
            v.x = fmaxf(v.x, 0.f); v.y = fmaxf(v.y, 0.f);
            v.z = fmaxf(v.z, 0.f); v.w = fmaxf(v.w, 0.f);
        }
        As[a_k4 + 0][a_row] = v.x; As[a_k4 + 1][a_row] = v.y;
        As[a_k4 + 2][a_row] = v.z; As[a_k4 + 3][a_row] = v.w;
#pragma unroll
        for (int r8 = 0; r8 < 8; r8++) {
            int idx = r8 * 256 + tid;
            int k = idx >> 7, jj = idx & 127;
            Bs[k][jj] = W[(kc + k) * 128 + jj];
        }
        __syncthreads();
#pragma unroll
        for (int k = 0; k < 16; k++) {
            float a[4], b[8];
#pragma unroll
            for (int i = 0; i < 4; i++) a[i] = As[k][ty * 4 + i];
#pragma unroll
            for (int jj = 0; jj < 8; jj++) b[jj] = Bs[k][tx * 8 + jj];
#pragma unroll
            for (int i = 0; i < 4; i++)
#pragma unroll
                for (int jj = 0; jj < 8; jj++) acc[i][jj] = fmaf(a[i], b[jj], acc[i][jj]);
        }
        __syncthreads();
    }
#pragma unroll
    for (int i = 0; i < 4; i++) {
        int n = nbase + ty * 4 + i;
        if (n >= NN) continue;
#pragma unroll
        for (int jj = 0; jj < 8; jj++) out[(size_t)n * 128 + tx * 8 + jj] = acc[i][jj];
    }
}

__global__ void gcn_init(const float* __restrict__ hW, const float* __restrict__ bvec,
                         const float* __restrict__ dinv, float* __restrict__ agg) {
    int idx = blockIdx.x * blockDim.x + threadIdx.x;
    if (idx >= NN * 128) return;
    int n = idx >> 7, jj = idx & 127;
    float di = dinv[n];
    agg[idx] = bvec[jj] + hW[idx] * di * di;
}

__global__ void gcn_agg(const float* __restrict__ hW, const int* __restrict__ src,
                        const int* __restrict__ dst, const float* __restrict__ dinv,
                        float* __restrict__ agg, int E) {
    int gw = (blockIdx.x * blockDim.x + threadIdx.x) >> 5;
    int lane = threadIdx.x & 31;
    if (gw >= E) return;
    int s = src[gw], d = dst[gw];
    float w = dinv[s] * dinv[d];
    float4 v = ((const float4*)(hW + (size_t)s * 128))[lane];
    float* p = agg + (size_t)d * 128 + lane * 4;
    atomicAdd(p + 0, v.x * w);
    atomicAdd(p + 1, v.y * w);
    atomicAdd(p + 2, v.z * w);
    atomicAdd(p + 3, v.w * w);
}

__global__ void gcn_gemm12(const float* __restrict__ A, const float* __restrict__ W2,
                           float* __restrict__ out12) {
    int warp = (blockIdx.x * blockDim.x + threadIdx.x) >> 5;
    int lane = threadIdx.x & 31;
    if (warp >= NN) return;
    float acc[12];
#pragma unroll
    for (int jj = 0; jj < 12; jj++) acc[jj] = 0.f;
    for (int k = lane; k < 128; k += 32) {
        float a = fmaxf(A[(size_t)warp * 128 + k], 0.f);
#pragma unroll
        for (int jj = 0; jj < 12; jj++) acc[jj] = fmaf(a, W2[k * 12 + jj], acc[jj]);
    }
#pragma unroll
    for (int jj = 0; jj < 12; jj++) {
        float v = acc[jj];
#pragma unroll
        for (int o = 16; o; o >>= 1) v += __shfl_down_sync(0xffffffffu, v, o);
        if (lane == 0) out12[(size_t)warp * 12 + jj] = v;
    }
}

__global__ void gcn_init12(const float* __restrict__ hW12, const float* __restrict__ b2,
                           const float* __restrict__ dinv, float* __restrict__ out) {
    int idx = blockIdx.x * blockDim.x + threadIdx.x;
    if (idx >= NN * 12) return;
    int n = idx / 12, jj = idx - n * 12;
    float di = dinv[n];
    out[idx] = b2[jj] + hW12[idx] * di * di;
}

__global__ void gcn_agg12(const float* __restrict__ hW12, const int* __restrict__ src,
                          const int* __restrict__ dst, const float* __restrict__ dinv,
                          float* __restrict__ out, int E) {
    int idx = blockIdx.x * blockDim.x + threadIdx.x;
    int e = idx >> 4;
    int jj = idx & 15;
    if (e >= E || jj >= 12) return;
    int s = src[e], d = dst[e];
    float w = dinv[s] * dinv[d];
    atomicAdd(&out[(size_t)d * 12 + jj], hW12[(size_t)s * 12 + jj] * w);
}

// ================= launch =================
extern "C" void kernel_launch(void* const* d_in, const int* in_sizes, int n_in,
                              void* d_out, int out_size) {
    const float* x    = (const float*)d_in[0];
    const int*   ei   = (const int*)d_in[1];
    const float* Wih0 = (const float*)d_in[2];
    const float* Whh0 = (const float*)d_in[3];
    const float* bih0 = (const float*)d_in[4];
    const float* bhh0 = (const float*)d_in[5];
    const float* Wih1 = (const float*)d_in[6];
    const float* Whh1 = (const float*)d_in[7];
    const float* bih1 = (const float*)d_in[8];
    const float* bhh1 = (const float*)d_in[9];
    const float* W0   = (const float*)d_in[10];
    const float* b0   = (const float*)d_in[11];
    const float* W1   = (const float*)d_in[12];
    const float* b1   = (const float*)d_in[13];
    const float* W2   = (const float*)d_in[14];
    const float* b2   = (const float*)d_in[15];
    float* out = (float*)d_out;

    int E = in_sizes[1] / 2;
    const int* src = ei;
    const int* dst = ei + E;

    float* S;
    cudaGetSymbolAddress((void**)&S, g_scratch);
    float* c0 = S;
    float* c1 = S + (size_t)NH;
    __half* HF = (__half*)(S + 2 * (size_t)NH);
    __half* h0[2] = { HF + 0 * (size_t)NH, HF + 1 * (size_t)NH };
    __half* h1[2] = { HF + 2 * (size_t)NH, HF + 3 * (size_t)NH };
    float* hfin = S + 4 * (size_t)NH;
    float* hw   = S + 5 * (size_t)NH;
    float* agg  = S + 6 * (size_t)NH;
    float* dinv = S + 7 * (size_t)NH;
    __half* Q = (__half*)(dinv + 65536);
    __half* B0  = Q;  Q += 8 * 144 * 64;
    __half* B1  = Q;  Q += 8 * 272 * 64;
    __half* Bt0 = Q;  Q += 8 * 144 * 64;
    __half* xp  = Q;  Q += (size_t)12 * NN * 16;
    __half* on  = Q;  Q += (size_t)NN * 16;

    zero_k<<<(2 * NH + 255) / 256, 256>>>(S, 2 * NH);
    prep_aug<<<(13 * NN * 16 + 255) / 256, 256>>>(x, xp, on);
    prep_B0<<<(8 * 144 * 64 + 255) / 256, 256>>>(Whh0, Wih0, bih0, bhh0, B0);
    prep_B1<<<(8 * 272 * 64 + 255) / 256, 256>>>(Wih1, Whh1, bih1, bhh1, B1);
    prep_B1t0<<<(8 * 144 * 64 + 255) / 256, 256>>>(Wih1, bih1, bhh1, Bt0);

    const int SM9  = 144 * 144 + 16 * 3072;   // 20736 + 49152 = 69888
    const int SM17 = 272 * 144 + 16 * 3072;   // 39168 + 49152 = 88320
    cudaFuncSetAttribute(lstm_mma<9>,  cudaFuncAttributeMaxDynamicSharedMemorySize, SM9);
    cudaFuncSetAttribute(lstm_mma<17>, cudaFuncAttributeMaxDynamicSharedMemorySize, SM17);

    dim3 lg(18, 8);
    int p = 0;
    for (int t = 0; t < TT; t++) {
        lstm_mma<9><<<lg, 512, SM9>>>(
            h0[p], (const __half*)nullptr, xp + (size_t)t * NN * 16,
            B0, t == 0 ? 8 : 0, c0, h0[1 - p]);
        if (t == 0) {
            lstm_mma<9><<<lg, 512, SM9>>>(
                h0[1 - p], (const __half*)nullptr, on, Bt0, 0, c1, h1[1 - p]);
        } else {
            lstm_mma<17><<<lg, 512, SM17>>>(
                h0[1 - p], h1[p], on, B1, 0, c1, h1[1 - p]);
        }
        p ^= 1;
    }
    recon_h<<<(NH + 255) / 256, 256>>>(h1[p], hfin);

    deg_init<<<(NN + 255) / 256, 256>>>(dinv);
    deg_count<<<(E + 255) / 256, 256>>>(dst, dinv, E);
    deg_rsqrt<<<(NN + 255) / 256, 256>>>(dinv);

    gcn_gemm<<<(NN + 63) / 64, 256>>>(hfin, W0, hw, 0);
    gcn_init<<<(NN * 128 + 255) / 256, 256>>>(hw, b0, dinv, agg);
    gcn_agg<<<(E + 7) / 8, 256>>>(hw, src, dst, dinv, agg, E);
    gcn_gemm<<<(NN + 63) / 64, 256>>>(agg, W1, hw, 1);
    gcn_init<<<(NN * 128 + 255) / 256, 256>>>(hw, b1, dinv, agg);
    gcn_agg<<<(E + 7) / 8, 256>>>(hw, src, dst, dinv, agg, E);
    gcn_gemm12<<<(NN * 32 + 255) / 256, 256>>>(agg, W2, hw);
    gcn_init12<<<(NN * 12 + 255) / 256, 256>>>(hw, b2, dinv, out);
    gcn_agg12<<<((size_t)E * 16 + 255) / 256, 256>>>(hw, src, dst, dinv, out, E);
}

// round 15
// speedup vs baseline: 2.7176x; 1.2501x over previous
#include <cuda_runtime.h>
#include <cuda_fp16.h>
#include <math.h>

#define TT   12
#define NN   50000
#define NH   (NN * 128)
#define MT512 98            // ceil(50000/512)
#define CSLOT 6500000       // 98*8*512*16 = 6,422,528 rounded up

// ================= scratch =================
// floats: c0 c1 (2*CSLOT) | h fp16 4 bufs (2NH fl) | hfin hw agg (3NH) | dinv 65536 |
// half tail: B0 (8*144*64) B1 (8*272*64) Bt0 (8*144*64) xpad (12*NN*16) ones (NN*16)
__device__ float g_scratch[2 * CSLOT + 5 * NH + 65536 + 5400000];

// ================= PTX helpers (portable, sm_80+) =================
__device__ __forceinline__ unsigned smem_u32(const void* p) {
    unsigned a;
    asm("{ .reg .u64 t; cvta.to.shared.u64 t, %1; cvt.u32.u64 %0, t; }" : "=r"(a) : "l"(p));
    return a;
}
__device__ __forceinline__ void cp16(unsigned dst, const void* src) {
    asm volatile("cp.async.cg.shared.global [%0], [%1], 16;" :: "r"(dst), "l"(src));
}
#define CP_COMMIT() asm volatile("cp.async.commit_group;" ::: "memory")
#define CP_WAIT0()  asm volatile("cp.async.wait_group 0;" ::: "memory")
#define CP_WAIT1()  asm volatile("cp.async.wait_group 1;" ::: "memory")
#define CP_WAIT2()  asm volatile("cp.async.wait_group 2;" ::: "memory")
#define CP_WAIT3()  asm volatile("cp.async.wait_group 3;" ::: "memory")

#define LDSM_X4(r0, r1, r2, r3, a) \
    asm volatile("ldmatrix.sync.aligned.m8n8.x4.shared.b16 {%0,%1,%2,%3}, [%4];" \
        : "=r"(r0), "=r"(r1), "=r"(r2), "=r"(r3) : "r"(a))

#define LDSM_X4T(r0, r1, r2, r3, a) \
    asm volatile("ldmatrix.sync.aligned.m8n8.x4.trans.shared.b16 {%0,%1,%2,%3}, [%4];" \
        : "=r"(r0), "=r"(r1), "=r"(r2), "=r"(r3) : "r"(a))

#define MMA16816F16(d, a, b) \
    asm volatile("mma.sync.aligned.m16n8k16.row.col.f32.f16.f16.f32 " \
        "{%0,%1,%2,%3}, {%4,%5,%6,%7}, {%8,%9}, {%0,%1,%2,%3};" \
        : "+f"((d)[0]), "+f"((d)[1]), "+f"((d)[2]), "+f"((d)[3]) \
        : "r"((a)[0]), "r"((a)[1]), "r"((a)[2]), "r"((a)[3]), "r"((b)[0]), "r"((b)[1]))

__device__ __forceinline__ float sigf(float z) { return __fdividef(1.0f, 1.0f + __expf(-z)); }
__device__ __forceinline__ float tanhf_(float z) { return __fdividef(2.0f, 1.0f + __expf(-2.0f * z)) - 1.0f; }

// ================= prep kernels =================
__global__ void zero_k(float* p, int n) {
    int i = blockIdx.x * blockDim.x + threadIdx.x;
    if (i < n) p[i] = 0.0f;
}

// xpad[t][n][16] = [x0, x1, 1, 0...]; t==12 slot -> ones[n][16] = [1, 0...]
__global__ void prep_aug(const float* __restrict__ x,
                         __half* __restrict__ xp, __half* __restrict__ on) {
    int idx = blockIdx.x * blockDim.x + threadIdx.x;
    if (idx >= 13 * NN * 16) return;
    int col = idx & 15;
    int rest = idx >> 4;
    int n = rest % NN;
    int t = rest / NN;
    float v = 0.f;
    if (t < 12) {
        if (col < 2) v = x[((size_t)n * TT + t) * 2 + col];
        else if (col == 2) v = 1.0f;
        xp[((size_t)t * NN + n) * 16 + col] = __float2half(v);
    } else {
        if (col == 0) v = 1.0f;
        on[(size_t)n * 16 + col] = __float2half(v);
    }
}

// staged B layout: [y(8)][k(BROWS)][col(64)], col = g*16 + jl, ro = g*128 + y*16 + jl
__global__ void prep_B0(const float* __restrict__ Whh0, const float* __restrict__ Wih0,
                        const float* __restrict__ bih0, const float* __restrict__ bhh0,
                        __half* __restrict__ B) {
    int idx = blockIdx.x * blockDim.x + threadIdx.x;      // 8*144*64
    if (idx >= 8 * 144 * 64) return;
    int y = idx / (144 * 64);
    int rem = idx - y * (144 * 64);
    int k = rem >> 6, col = rem & 63;
    int ro = (col >> 4) * 128 + y * 16 + (col & 15);
    float w = 0.f;
    if (k < 128) w = Whh0[ro * 128 + k];
    else if (k == 128) w = Wih0[ro * 2 + 0];
    else if (k == 129) w = Wih0[ro * 2 + 1];
    else if (k == 130) w = bih0[ro] + bhh0[ro];
    B[idx] = __float2half(w);
}

__global__ void prep_B1(const float* __restrict__ Wih1, const float* __restrict__ Whh1,
                        const float* __restrict__ bih1, const float* __restrict__ bhh1,
                        __half* __restrict__ B) {
    int idx = blockIdx.x * blockDim.x + threadIdx.x;      // 8*272*64
    if (idx >= 8 * 272 * 64) return;
    int y = idx / (272 * 64);
    int rem = idx - y * (272 * 64);
    int k = rem >> 6, col = rem & 63;
    int ro = (col >> 4) * 128 + y * 16 + (col & 15);
    float w = 0.f;
    if (k < 128) w = Wih1[ro * 128 + k];
    else if (k < 256) w = Whh1[ro * 128 + (k - 128)];
    else if (k == 256) w = bih1[ro] + bhh1[ro];
    B[idx] = __float2half(w);
}

__global__ void prep_B1t0(const float* __restrict__ Wih1,
                          const float* __restrict__ bih1, const float* __restrict__ bhh1,
                          __half* __restrict__ B) {
    int idx = blockIdx.x * blockDim.x + threadIdx.x;      // 8*144*64
    if (idx >= 8 * 144 * 64) return;
    int y = idx / (144 * 64);
    int rem = idx - y * (144 * 64);
    int k = rem >> 6, col = rem & 63;
    int ro = (col >> 4) * 128 + y * 16 + (col & 15);
    float w = 0.f;
    if (k < 128) w = Wih1[ro * 128 + k];
    else if (k == 128) w = bih1[ro] + bhh1[ro];
    B[idx] = __float2half(w);
}

__global__ void deg_init(float* deg) {
    int i = blockIdx.x * blockDim.x + threadIdx.x;
    if (i < NN) deg[i] = 1.0f;
}
__global__ void deg_count(const int* __restrict__ dst, float* deg, int E) {
    int i = blockIdx.x * blockDim.x + threadIdx.x;
    if (i < E) atomicAdd(&deg[dst[i]], 1.0f);
}
__global__ void deg_rsqrt(float* deg) {
    int i = blockIdx.x * blockDim.x + threadIdx.x;
    if (i < NN) deg[i] = rsqrtf(deg[i]);
}

__global__ void recon_h(const __half* __restrict__ hh, float* __restrict__ out) {
    int i = blockIdx.x * blockDim.x + threadIdx.x;
    if (i < NH) out[i] = __half2float(hh[i]);
}

// ================= LSTM step: fp16 single chain, 16 m-warps x 64 cols =================
// grid (18, 8). 512 thr = 16 warps, 32 rows/warp; m-tile 512 rows. Zero m-loop barriers.
// B resident smem [k][64] stride 144B (fp16). A: warp-private 4-stage cp.async ring
// (stage 1536B, rows stride 48B). Aug columns fold x and bias into the GEMM.
// c lives in a private slot layout -> fully coalesced float4 access.
template <int NK>
__global__ __launch_bounds__(512, 1)
void lstm_mma(const __half* __restrict__ A0, const __half* __restrict__ A1,
              const __half* __restrict__ AG,
              const __half* __restrict__ B_st,
              int kstart,
              float* __restrict__ c,
              __half* __restrict__ Oh) {
    extern __shared__ char smem[];
    unsigned sb = smem_u32(smem);
    const int BROWS = NK * 16;
    const unsigned BSZ = (unsigned)(BROWS * 144);
    int tid = threadIdx.x, lane = tid & 31, wid = tid >> 5;
    int y = blockIdx.y;

    // ---- B resident load (once) ----
    {
        size_t bbase = (size_t)y * BROWS * 64;
        for (int i = tid; i < BROWS * 8; i += 512) {
            int k = i >> 3, seg = i & 7;
            cp16(sb + (unsigned)(k * 144 + seg * 16),
                 B_st + bbase + (size_t)k * 64 + seg * 8);
        }
        CP_COMMIT();
        CP_WAIT0();
    }
    __syncthreads();

    unsigned ring = sb + BSZ + (unsigned)wid * 6144u;   // 4 stages x 1536B
    unsigned a_ad[2];
#pragma unroll
    for (int mt = 0; mt < 2; mt++)
        a_ad[mt] = (unsigned)((mt * 16 + (lane & 15)) * 48 + (lane >> 4) * 16);
    int bkk = ((lane >> 3) & 1) * 8 + (lane & 7);
    unsigned bcol8 = (unsigned)((lane >> 4) * 8 * 2);

    int q = lane & 3;

    for (int m = blockIdx.x; m < MT512; m += gridDim.x) {
        int nbase = m * 512;
        int arow = nbase + wid * 32 + lane;
        if (arow >= NN) arow = NN - 1;

        auto loadA = [&](int kn) {
            const __half* H;
            size_t so;
            if (kn < 8)                   { H = A0; so = (size_t)arow * 128 + kn * 16; }
            else if (NK == 17 && kn < 16) { H = A1; so = (size_t)arow * 128 + (kn - 8) * 16; }
            else                          { H = AG; so = (size_t)arow * 16; }
            unsigned d = ring + (unsigned)((kn & 3) * 1536 + lane * 48);
            cp16(d,       H + so);
            cp16(d + 16u, H + so + 8);
            CP_COMMIT();
        };

        float acc[2][8][4];
#pragma unroll
        for (int mt = 0; mt < 2; mt++)
#pragma unroll
            for (int nf = 0; nf < 8; nf++)
#pragma unroll
                for (int i = 0; i < 4; i++) acc[mt][nf][i] = 0.f;

        // prologue: 3 chunks in flight
        loadA(kstart);
        if (kstart + 1 < NK) loadA(kstart + 1);
        if (kstart + 2 < NK) loadA(kstart + 2);

        for (int kc = kstart; kc < NK; kc++) {
            if (kc + 3 < NK)      { loadA(kc + 3); CP_WAIT3(); }
            else if (kc + 2 < NK) { CP_WAIT2(); }
            else if (kc + 1 < NK) { CP_WAIT1(); }
            else                  { CP_WAIT0(); }

            unsigned abuf = ring + (unsigned)((kc & 3) * 1536);
            unsigned ah[2][4];
#pragma unroll
            for (int mt = 0; mt < 2; mt++)
                LDSM_X4(ah[mt][0], ah[mt][1], ah[mt][2], ah[mt][3], abuf + a_ad[mt]);

            unsigned bbase_k = sb + (unsigned)((kc * 16 + bkk) * 144);
#pragma unroll
            for (int half = 0; half < 2; half++) {
                unsigned bh[4][2];
#pragma unroll
                for (int np = 0; np < 2; np++) {
                    unsigned ad = bbase_k + (unsigned)(half * 64 + np * 32) + bcol8;
                    LDSM_X4T(bh[np * 2][0], bh[np * 2][1], bh[np * 2 + 1][0], bh[np * 2 + 1][1], ad);
                }
#pragma unroll
                for (int mt = 0; mt < 2; mt++)
#pragma unroll
                    for (int nf4 = 0; nf4 < 4; nf4++)
                        MMA16816F16(acc[mt][half * 4 + nf4], ah[mt], bh[nf4]);
            }
        }

        // ---- in-register epilogue; c in coalesced slot layout ----
        size_t cbase = (((size_t)m * 8 + y) * 512 + tid) * 16;
        int jb0 = y * 16 + q * 2;
#pragma unroll
        for (int mt = 0; mt < 2; mt++)
#pragma unroll
            for (int rp = 0; rp < 2; rp++) {
                int n = nbase + wid * 32 + mt * 16 + rp * 8 + (lane >> 2);
                float4 cv = *(const float4*)(c + cbase + (mt * 8 + rp * 4));
                float cres[4], hres[4];
#pragma unroll
                for (int jli = 0; jli < 4; jli++) {
                    int jh = jli >> 1;
                    int par = jli & 1;
                    int ridx = rp * 2 + par;
                    float zi = acc[mt][0 + jh][ridx];
                    float zf = acc[mt][2 + jh][ridx];
                    float zg = acc[mt][4 + jh][ridx];
                    float zo = acc[mt][6 + jh][ridx];
                    float cp_ = (&cv.x)[jli];
                    float cn = sigf(zf) * cp_ + sigf(zi) * tanhf_(zg);
                    cres[jli] = cn;
                    hres[jli] = sigf(zo) * tanhf_(cn);
                }
                *(float4*)(c + cbase + (mt * 8 + rp * 4)) =
                    make_float4(cres[0], cres[1], cres[2], cres[3]);
                if (n < NN) {
                    *(__half2*)(Oh + (size_t)n * 128 + jb0) =
                        __floats2half2_rn(hres[0], hres[1]);
                    *(__half2*)(Oh + (size_t)n * 128 + jb0 + 8) =
                        __floats2half2_rn(hres[2], hres[3]);
                }
            }
        // no __syncthreads: ring warp-private, B read-only, epilogue register-local
    }
}

// ================= GCN (fp32, proven) =================
__global__ __launch_bounds__(256)
void gcn_gemm(const float* __restrict__ A, const float* __restrict__ W,
              float* __restrict__ out, int relu) {
    __shared__ float As[16][68];
    __shared__ float Bs[16][128];
    int tid = threadIdx.x;
    int ty = tid >> 4, tx = tid & 15;
    int nbase = blockIdx.x * 64;
    float acc[4][8];
#pragma unroll
    for (int i = 0; i < 4; i++)
#pragma unroll
        for (int j = 0; j < 8; j++) acc[i][j] = 0.f;
    int a_row = tid >> 2;
    int a_k4 = (tid & 3) * 4;
    for (int kc = 0; kc < 128; kc += 16) {
        int n = nbase + a_row;
        float4 v = make_float4(0.f, 0.f, 0.f, 0.f);
        if (n < NN) v = *(const float4*)(A + (size_t)n * 128 + kc + a_k4);
        if (relu) {
            v.x = fmaxf(v.x, 0.f); v.y = fmaxf(v.y, 0.f);
            v.z = fmaxf(v.z, 0.f); v.w = fmaxf(v.w, 0.f);
        }
        As[a_k4 + 0][a_row] = v.x; As[a_k4 + 1][a_row] = v.y;
        As[a_k4 + 2][a_row] = v.z; As[a_k4 + 3][a_row] = v.w;
#pragma unroll
        for (int r8 = 0; r8 < 8; r8++) {
            int idx = r8 * 256 + tid;
            int k = idx >> 7, jj = idx & 127;
            Bs[k][jj] = W[(kc + k) * 128 + jj];
        }
        __syncthreads();
#pragma unroll
        for (int k = 0; k < 16; k++) {
            float a[4], b[8];
#pragma unroll
            for (int i = 0; i < 4; i++) a[i] = As[k][ty * 4 + i];
#pragma unroll
            for (int jj = 0; jj < 8; jj++) b[jj] = Bs[k][tx * 8 + jj];
#pragma unroll
            for (int i = 0; i < 4; i++)
#pragma unroll
                for (int jj = 0; jj < 8; jj++) acc[i][jj] = fmaf(a[i], b[jj], acc[i][jj]);
        }
        __syncthreads();
    }
#pragma unroll
    for (int i = 0; i < 4; i++) {
        int n = nbase + ty * 4 + i;
        if (n >= NN) continue;
#pragma unroll
        for (int jj = 0; jj < 8; jj++) out[(size_t)n * 128 + tx * 8 + jj] = acc[i][jj];
    }
}

__global__ void gcn_init(const float* __restrict__ hW, const float* __restrict__ bvec,
                         const float* __restrict__ dinv, float* __restrict__ agg) {
    int idx = blockIdx.x * blockDim.x + threadIdx.x;
    if (idx >= NN * 128) return;
    int n = idx >> 7, jj = idx & 127;
    float di = dinv[n];
    agg[idx] = bvec[jj] + hW[idx] * di * di;
}

__global__ void gcn_agg(const float* __restrict__ hW, const int* __restrict__ src,
                        const int* __restrict__ dst, const float* __restrict__ dinv,
                        float* __restrict__ agg, int E) {
    int gw = (blockIdx.x * blockDim.x + threadIdx.x) >> 5;
    int lane = threadIdx.x & 31;
    if (gw >= E) return;
    int s = src[gw], d = dst[gw];
    float w = dinv[s] * dinv[d];
    float4 v = ((const float4*)(hW + (size_t)s * 128))[lane];
    float* p = agg + (size_t)d * 128 + lane * 4;
    atomicAdd(p + 0, v.x * w);
    atomicAdd(p + 1, v.y * w);
    atomicAdd(p + 2, v.z * w);
    atomicAdd(p + 3, v.w * w);
}

__global__ void gcn_gemm12(const float* __restrict__ A, const float* __restrict__ W2,
                           float* __restrict__ out12) {
    int warp = (blockIdx.x * blockDim.x + threadIdx.x) >> 5;
    int lane = threadIdx.x & 31;
    if (warp >= NN) return;
    float acc[12];
#pragma unroll
    for (int jj = 0; jj < 12; jj++) acc[jj] = 0.f;
    for (int k = lane; k < 128; k += 32) {
        float a = fmaxf(A[(size_t)warp * 128 + k], 0.f);
#pragma unroll
        for (int jj = 0; jj < 12; jj++) acc[jj] = fmaf(a, W2[k * 12 + jj], acc[jj]);
    }
#pragma unroll
    for (int jj = 0; jj < 12; jj++) {
        float v = acc[jj];
#pragma unroll
        for (int o = 16; o; o >>= 1) v += __shfl_down_sync(0xffffffffu, v, o);
        if (lane == 0) out12[(size_t)warp * 12 + jj] = v;
    }
}

__global__ void gcn_init12(const float* __restrict__ hW12, const float* __restrict__ b2,
                           const float* __restrict__ dinv, float* __restrict__ out) {
    int idx = blockIdx.x * blockDim.x + threadIdx.x;
    if (idx >= NN * 12) return;
    int n = idx / 12, jj = idx - n * 12;
    float di = dinv[n];
    out[idx] = b2[jj] + hW12[idx] * di * di;
}

__global__ void gcn_agg12(const float* __restrict__ hW12, const int* __restrict__ src,
                          const int* __restrict__ dst, const float* __restrict__ dinv,
                          float* __restrict__ out, int E) {
    int idx = blockIdx.x * blockDim.x + threadIdx.x;
    int e = idx >> 4;
    int jj = idx & 15;
    if (e >= E || jj >= 12) return;
    int s = src[e], d = dst[e];
    float w = dinv[s] * dinv[d];
    atomicAdd(&out[(size_t)d * 12 + jj], hW12[(size_t)s * 12 + jj] * w);
}

// ================= launch =================
extern "C" void kernel_launch(void* const* d_in, const int* in_sizes, int n_in,
                              void* d_out, int out_size) {
    const float* x    = (const float*)d_in[0];
    const int*   ei   = (const int*)d_in[1];
    const float* Wih0 = (const float*)d_in[2];
    const float* Whh0 = (const float*)d_in[3];
    const float* bih0 = (const float*)d_in[4];
    const float* bhh0 = (const float*)d_in[5];
    const float* Wih1 = (const float*)d_in[6];
    const float* Whh1 = (const float*)d_in[7];
    const float* bih1 = (const float*)d_in[8];
    const float* bhh1 = (const float*)d_in[9];
    const float* W0   = (const float*)d_in[10];
    const float* b0   = (const float*)d_in[11];
    const float* W1   = (const float*)d_in[12];
    const float* b1   = (const float*)d_in[13];
    const float* W2   = (const float*)d_in[14];
    const float* b2   = (const float*)d_in[15];
    float* out = (float*)d_out;

    int E = in_sizes[1] / 2;
    const int* src = ei;
    const int* dst = ei + E;

    float* S;
    cudaGetSymbolAddress((void**)&S, g_scratch);
    float* c0 = S;
    float* c1 = S + (size_t)CSLOT;
    __half* HF = (__half*)(S + 2 * (size_t)CSLOT);
    __half* h0[2] = { HF + 0 * (size_t)NH, HF + 1 * (size_t)NH };
    __half* h1[2] = { HF + 2 * (size_t)NH, HF + 3 * (size_t)NH };
    float* hfin = S + 2 * (size_t)CSLOT + 2 * (size_t)NH;
    float* hw   = hfin + (size_t)NH;
    float* agg  = hw + (size_t)NH;
    float* dinv = agg + (size_t)NH;
    __half* Q = (__half*)(dinv + 65536);
    __half* B0  = Q;  Q += 8 * 144 * 64;
    __half* B1  = Q;  Q += 8 * 272 * 64;
    __half* Bt0 = Q;  Q += 8 * 144 * 64;
    __half* xp  = Q;  Q += (size_t)12 * NN * 16;
    __half* on  = Q;  Q += (size_t)NN * 16;

    zero_k<<<(2 * CSLOT + 255) / 256, 256>>>(S, 2 * CSLOT);
    prep_aug<<<(13 * NN * 16 + 255) / 256, 256>>>(x, xp, on);
    prep_B0<<<(8 * 144 * 64 + 255) / 256, 256>>>(Whh0, Wih0, bih0, bhh0, B0);
    prep_B1<<<(8 * 272 * 64 + 255) / 256, 256>>>(Wih1, Whh1, bih1, bhh1, B1);
    prep_B1t0<<<(8 * 144 * 64 + 255) / 256, 256>>>(Wih1, bih1, bhh1, Bt0);

    const int SM9  = 144 * 144 + 16 * 6144;   // 20736 + 98304 = 119040
    const int SM17 = 272 * 144 + 16 * 6144;   // 39168 + 98304 = 137472
    cudaFuncSetAttribute(lstm_mma<9>,  cudaFuncAttributeMaxDynamicSharedMemorySize, SM9);
    cudaFuncSetAttribute(lstm_mma<17>, cudaFuncAttributeMaxDynamicSharedMemorySize, SM17);

    dim3 lg(18, 8);
    int p = 0;
    for (int t = 0; t < TT; t++) {
        lstm_mma<9><<<lg, 512, SM9>>>(
            h0[p], (const __half*)nullptr, xp + (size_t)t * NN * 16,
            B0, t == 0 ? 8 : 0, c0, h0[1 - p]);
        if (t == 0) {
            lstm_mma<9><<<lg, 512, SM9>>>(
                h0[1 - p], (const __half*)nullptr, on, Bt0, 0, c1, h1[1 - p]);
        } else {
            lstm_mma<17><<<lg, 512, SM17>>>(
                h0[1 - p], h1[p], on, B1, 0, c1, h1[1 - p]);
        }
        p ^= 1;
    }
    recon_h<<<(NH + 255) / 256, 256>>>(h1[p], hfin);

    deg_init<<<(NN + 255) / 256, 256>>>(dinv);
    deg_count<<<(E + 255) / 256, 256>>>(dst, dinv, E);
    deg_rsqrt<<<(NN + 255) / 256, 256>>>(dinv);

    gcn_gemm<<<(NN + 63) / 64, 256>>>(hfin, W0, hw, 0);
    gcn_init<<<(NN * 128 + 255) / 256, 256>>>(hw, b0, dinv, agg);
    gcn_agg<<<(E + 7) / 8, 256>>>(hw, src, dst, dinv, agg, E);
    gcn_gemm<<<(NN + 63) / 64, 256>>>(agg, W1, hw, 1);
    gcn_init<<<(NN * 128 + 255) / 256, 256>>>(hw, b1, dinv, agg);
    gcn_agg<<<(E + 7) / 8, 256>>>(hw, src, dst, dinv, agg, E);
    gcn_gemm12<<<(NN * 32 + 255) / 256, 256>>>(agg, W2, hw);
    gcn_init12<<<(NN * 12 + 255) / 256, 256>>>(hw, b2, dinv, out);
    gcn_agg12<<<((size_t)E * 16 + 255) / 256, 256>>>(hw, src, dst, dinv, out, E);
}